// round 13
// baseline (speedup 1.0000x reference)
#include <cuda_runtime.h>

// Problem constants
#define NN 13          // nodes
#define DD 16          // feature dim
#define NB 16          // batch elements per block
#define TPB 256        // threads per block (16 per batch element)

// Per-batch shared region, stride RS floats (RS % 32 == 8).
//  [0..832)     adj padded: 4 ch x 13 rows x stride16
//               (decoder reuse: temp kk0 [0..208), kk1 [208..416), recon [416..754))
//  [832..1040)  X0 buffer (13 x 16)
//  [1040..1248) X1 buffer (13 x 16)
#define RS    1256
#define X0OFF 832
#define X1OFF 1040

// Block-common weights region
#define WB     (16*RS)         // 20096
#define OW     (WB)            // init_weight [m][c] natural        208
#define OW0    (WB+208)        // mlp_w0 transposed [l][dp][c]     1024
#define OW1    (WB+1232)       // mlp_w1 transposed                1024
#define OB0    (WB+2256)       // mlp_b0 [l][16]                     64
#define OB1    (WB+2320)       //                                    64
#define OF1    (WB+2384)       // fc1_w transposed [dp][c]          256
#define OF2    (WB+2640)       //                                   256
#define OF1B   (WB+2896)       //                                    16
#define OF2B   (WB+2912)       //                                    16
#define ODEC   (WB+2928)       // dec_w transposed [k][li][d]      1024
#define ODECB  (WB+3952)       //                                    64
#define OBNI   (WB+4016)       // bn_in  {scale,bias} [l][n][2]     104
#define OBNO   (WB+4120)       // bn_out {scale,bias}               104
#define OEPS   (WB+4224)       // 1+eps [4]                           4
#define SH_FLOATS (WB+4228)    // 24324 floats = 97296 B -> 2 blocks/SM
#define SMEM_BYTES (SH_FLOATS*4)

// Output layout: recon (B,4,13,13) | mu (B,13,16) | logvar (B,13,16)
#define RECON_ELEMS (676ull)
#define MU_OFF  (32768ull*676ull)
#define LV_OFF  (MU_OFF + 32768ull*208ull)

// Triangular pair decode tables for p in [0,91): (n<=m)
__constant__ unsigned char PN[91] = {
 0,0,0,0,0,0,0,0,0,0,0,0,0,
 1,1,1,1,1,1,1,1,1,1,1,1,
 2,2,2,2,2,2,2,2,2,2,2,
 3,3,3,3,3,3,3,3,3,3,
 4,4,4,4,4,4,4,4,4,
 5,5,5,5,5,5,5,5,
 6,6,6,6,6,6,6,
 7,7,7,7,7,7,
 8,8,8,8,8,
 9,9,9,9,
 10,10,10,
 11,11,
 12};
__constant__ unsigned char PM[91] = {
 0,1,2,3,4,5,6,7,8,9,10,11,12,
 1,2,3,4,5,6,7,8,9,10,11,12,
 2,3,4,5,6,7,8,9,10,11,12,
 3,4,5,6,7,8,9,10,11,12,
 4,5,6,7,8,9,10,11,12,
 5,6,7,8,9,10,11,12,
 6,7,8,9,10,11,12,
 7,8,9,10,11,12,
 8,9,10,11,12,
 9,10,11,12,
 10,11,12,
 11,12,
 12};

__global__ void __launch_bounds__(TPB, 2) vae_kernel(
    const float* __restrict__ adj,
    const float* __restrict__ initW,
    const float* __restrict__ eps_param,
    const float* __restrict__ mlp_w0,
    const float* __restrict__ mlp_b0,
    const float* __restrict__ mlp_w1,
    const float* __restrict__ mlp_b1,
    const float* __restrict__ bn_in_gamma,
    const float* __restrict__ bn_in_beta,
    const float* __restrict__ bn_in_mean,
    const float* __restrict__ bn_in_var,
    const float* __restrict__ bn_out_gamma,
    const float* __restrict__ bn_out_beta,
    const float* __restrict__ bn_out_mean,
    const float* __restrict__ bn_out_var,
    const float* __restrict__ fc1_w,
    const float* __restrict__ fc1_b,
    const float* __restrict__ fc2_w,
    const float* __restrict__ fc2_b,
    const float* __restrict__ dec_w,
    const float* __restrict__ dec_b,
    float* __restrict__ out)
{
    extern __shared__ float sh[];
    const int tid = threadIdx.x;

    // ---------------- Phase A: cooperative loads ----------------
    {
        const float4* src = reinterpret_cast<const float4*>(adj + (size_t)blockIdx.x * NB * 676);
        for (int c = tid; c < NB * 169; c += TPB) {
            int bl = c / 169;
            int r  = c - bl * 169;
            float4 v = src[c];
            float vv[4] = {v.x, v.y, v.z, v.w};
            int e = 4 * r;
            #pragma unroll
            for (int j = 0; j < 4; ++j) {
                int ee = e + j;
                int ch = ee / 169;
                int p  = ee - ch * 169;
                int n  = p / 13;
                int m  = p - n * 13;
                sh[bl * RS + ch * 208 + n * 16 + m] = vv[j];
            }
        }
    }
    for (int j = tid; j < 208; j += TPB) sh[OW + j] = initW[j];
    for (int j = tid; j < 1024; j += TPB) {
        int l = j >> 8, r = j & 255, dp = r >> 4, c = r & 15;
        sh[OW0 + j] = mlp_w0[(l << 8) + (c << 4) + dp];
        sh[OW1 + j] = mlp_w1[(l << 8) + (c << 4) + dp];
        sh[ODEC + j] = dec_w[(l << 8) + (c << 4) + dp];   // [k][li][d] <- dec_w[k][d][li]
    }
    for (int j = tid; j < 64; j += TPB) {
        sh[OB0 + j] = mlp_b0[j];
        sh[OB1 + j] = mlp_b1[j];
        sh[ODECB + j] = dec_b[j];
    }
    for (int j = tid; j < 256; j += TPB) {
        int dp = j >> 4, c = j & 15;
        sh[OF1 + j] = fc1_w[(c << 4) + dp];
        sh[OF2 + j] = fc2_w[(c << 4) + dp];
    }
    for (int j = tid; j < 16; j += TPB) {
        sh[OF1B + j] = fc1_b[j];
        sh[OF2B + j] = fc2_b[j];
    }
    for (int j = tid; j < 52; j += TPB) {
        float s = bn_in_gamma[j] * rsqrtf(bn_in_var[j] + 1e-5f);
        sh[OBNI + 2*j]     = s;
        sh[OBNI + 2*j + 1] = bn_in_beta[j] - bn_in_mean[j] * s;
        float so = bn_out_gamma[j] * rsqrtf(bn_out_var[j] + 1e-5f);
        sh[OBNO + 2*j]     = so;
        sh[OBNO + 2*j + 1] = bn_out_beta[j] - bn_out_mean[j] * so;
    }
    for (int j = tid; j < 4; j += TPB) sh[OEPS + j] = 1.0f + eps_param[j];
    __syncthreads();

    // ---------------- Phase B: per-batch work (warp-local) ----------------
    // Warp = 2 batches x 16 threads. Thread owns (col pair d0, node half nh).
    const int lane = tid & 31;
    const int warp = tid >> 5;
    const int grp  = lane >> 4;        // batch within warp (0..1)
    const int t16  = lane & 15;
    const int t8   = t16 & 7;          // column-pair index
    const int nh   = t16 >> 3;         // node half (0,1)
    const int bl   = warp * 2 + grp;
    const size_t b = (size_t)blockIdx.x * NB + bl;
    float* R  = sh + bl * RS;
    const int d0   = 2 * t8;
    const int iCh  = t8 >> 1;          // adj channel for owned col pair
    const int nb0  = nh * 6;           // 7 iters: n = nb0..nb0+6 (n=6 duplicated, identical values)

    float* cur = R + X1OFF;            // x lives here at layer start
    float* alt = R + X0OFF;

    // S[n][*] = sum_ch adj[ch][n][*]  into alt, padded rows
    for (int idx = t16; idx < 52; idx += 16) {
        int n = idx >> 2, q = idx & 3;
        const float* p0 = R + n * 16 + q * 4;
        float4 a  = *reinterpret_cast<const float4*>(p0);
        float4 c1 = *reinterpret_cast<const float4*>(p0 + 208);
        float4 c2 = *reinterpret_cast<const float4*>(p0 + 416);
        float4 c3 = *reinterpret_cast<const float4*>(p0 + 624);
        float4 s;
        s.x = a.x + c1.x + c2.x + c3.x;
        s.y = a.y + c1.y + c2.y + c3.y;
        s.z = a.z + c1.z + c2.z + c3.z;
        s.w = a.w + c1.w + c2.w + c3.w;
        *reinterpret_cast<float4*>(alt + n * 16 + q * 4) = s;
    }
    __syncwarp();

    // init: x = S @ W   (alt -> cur), own n-half
    #pragma unroll
    for (int i = 0; i < 7; ++i) {
        int n = nb0 + i;
        float a0 = 0.f, a1 = 0.f;
        const float* Sr = alt + n * 16;
        #pragma unroll
        for (int m = 0; m < NN; ++m) {
            float s = Sr[m];
            float2 w = *reinterpret_cast<const float2*>(&sh[OW + m * 16 + d0]);
            a0 = fmaf(s, w.x, a0);
            a1 = fmaf(s, w.y, a1);
        }
        *reinterpret_cast<float2*>(&cur[n * 16 + d0]) = make_float2(a0, a1);
    }
    __syncwarp();

    // 4 GIN layers
    #pragma unroll 1
    for (int l = 0; l < 4; ++l) {
        const float ep = sh[OEPS + l];
        const float* A = R + iCh * 208;

        // agg: alt[n][d0:2] = ep*x[n] + (A @ x)[n]   (cur -> alt)
        #pragma unroll
        for (int i = 0; i < 7; ++i) {
            int n = nb0 + i;
            const float* Ar = A + n * 16;
            float2 xn = *reinterpret_cast<const float2*>(&cur[n * 16 + d0]);
            float a0 = ep * xn.x, a1 = ep * xn.y;
            #pragma unroll
            for (int m = 0; m < NN; ++m) {
                float av = Ar[m];
                float2 xm = *reinterpret_cast<const float2*>(&cur[m * 16 + d0]);
                a0 = fmaf(av, xm.x, a0);
                a1 = fmaf(av, xm.y, a1);
            }
            *reinterpret_cast<float2*>(&alt[n * 16 + d0]) = make_float2(a0, a1);
        }
        __syncwarp();

        // MLP1 + bn_in + leaky: alt -> cur
        {
            const float* Wt = sh + OW0 + (l << 8);
            float2 bb = *reinterpret_cast<const float2*>(&sh[OB0 + (l << 4) + d0]);
            #pragma unroll
            for (int i = 0; i < 7; ++i) {
                int n = nb0 + i;
                const float* Xr = alt + n * 16;
                float a0 = bb.x, a1 = bb.y;
                #pragma unroll
                for (int dp = 0; dp < DD; ++dp) {
                    float xv = Xr[dp];
                    float2 w = *reinterpret_cast<const float2*>(&Wt[dp * 16 + d0]);
                    a0 = fmaf(xv, w.x, a0);
                    a1 = fmaf(xv, w.y, a1);
                }
                float2 bn = *reinterpret_cast<const float2*>(&sh[OBNI + l * 26 + n * 2]);
                a0 = fmaf(a0, bn.x, bn.y);
                a1 = fmaf(a1, bn.x, bn.y);
                a0 = (a0 >= 0.f) ? a0 : 0.01f * a0;
                a1 = (a1 >= 0.f) ? a1 : 0.01f * a1;
                *reinterpret_cast<float2*>(&cur[n * 16 + d0]) = make_float2(a0, a1);
            }
        }
        __syncwarp();

        // MLP2 + bn_out + leaky: cur -> alt
        {
            const float* Wt = sh + OW1 + (l << 8);
            float2 bb = *reinterpret_cast<const float2*>(&sh[OB1 + (l << 4) + d0]);
            #pragma unroll
            for (int i = 0; i < 7; ++i) {
                int n = nb0 + i;
                const float* Xr = cur + n * 16;
                float a0 = bb.x, a1 = bb.y;
                #pragma unroll
                for (int dp = 0; dp < DD; ++dp) {
                    float xv = Xr[dp];
                    float2 w = *reinterpret_cast<const float2*>(&Wt[dp * 16 + d0]);
                    a0 = fmaf(xv, w.x, a0);
                    a1 = fmaf(xv, w.y, a1);
                }
                float2 bn = *reinterpret_cast<const float2*>(&sh[OBNO + l * 26 + n * 2]);
                a0 = fmaf(a0, bn.x, bn.y);
                a1 = fmaf(a1, bn.x, bn.y);
                a0 = (a0 >= 0.f) ? a0 : 0.01f * a0;
                a1 = (a1 >= 0.f) ? a1 : 0.01f * a1;
                *reinterpret_cast<float2*>(&alt[n * 16 + d0]) = make_float2(a0, a1);
            }
        }
        __syncwarp();

        // new x is in alt
        float* tmp = cur; cur = alt; alt = tmp;
    }

    // fc1 -> mu (alt + gmem), fc2 -> logvar (gmem). x is in cur.
    {
        float2 fb = *reinterpret_cast<const float2*>(&sh[OF1B + d0]);
        float* muG = out + MU_OFF + b * 208;
        #pragma unroll
        for (int i = 0; i < 7; ++i) {
            int n = nb0 + i;
            const float* Xr = cur + n * 16;
            float a0 = fb.x, a1 = fb.y;
            #pragma unroll
            for (int dp = 0; dp < DD; ++dp) {
                float xv = Xr[dp];
                float2 w = *reinterpret_cast<const float2*>(&sh[OF1 + dp * 16 + d0]);
                a0 = fmaf(xv, w.x, a0);
                a1 = fmaf(xv, w.y, a1);
            }
            *reinterpret_cast<float2*>(&muG[n * 16 + d0]) = make_float2(a0, a1);
            *reinterpret_cast<float2*>(&alt[n * 16 + d0]) = make_float2(a0, a1);
        }
    }
    {
        float2 fb = *reinterpret_cast<const float2*>(&sh[OF2B + d0]);
        float* lvG = out + LV_OFF + b * 208;
        #pragma unroll
        for (int i = 0; i < 7; ++i) {
            int n = nb0 + i;
            const float* Xr = cur + n * 16;
            float a0 = fb.x, a1 = fb.y;
            #pragma unroll
            for (int dp = 0; dp < DD; ++dp) {
                float xv = Xr[dp];
                float2 w = *reinterpret_cast<const float2*>(&sh[OF2 + dp * 16 + d0]);
                a0 = fmaf(xv, w.x, a0);
                a1 = fmaf(xv, w.y, a1);
            }
            *reinterpret_cast<float2*>(&lvG[n * 16 + d0]) = make_float2(a0, a1);
        }
    }
    __syncwarp();   // mu (alt) visible to whole group

    // Decoder in two k-chunks; temp at R[0..416), recon scratch at R[416..754)
    float* outR = out + b * RECON_ELEMS;
    float* Rc = R + 416;
    #pragma unroll 1
    for (int c = 0; c < 2; ++c) {
        #pragma unroll
        for (int kk = 0; kk < 2; ++kk) {
            int k = 2 * c + kk;
            const float* Dt = sh + ODEC + (k << 8);
            float2 db = *reinterpret_cast<const float2*>(&sh[ODECB + (k << 4) + d0]);
            #pragma unroll
            for (int i = 0; i < 7; ++i) {
                int n = nb0 + i;
                const float* Zr = alt + n * 16;
                float a0 = db.x, a1 = db.y;
                #pragma unroll
                for (int li = 0; li < DD; ++li) {
                    float mv = Zr[li];
                    float2 w = *reinterpret_cast<const float2*>(&Dt[li * 16 + d0]);
                    a0 = fmaf(mv, w.x, a0);
                    a1 = fmaf(mv, w.y, a1);
                }
                *reinterpret_cast<float2*>(&R[kk * 208 + n * 16 + d0]) = make_float2(a0, a1);
            }
        }
        __syncwarp();
        // recon = relu(temp @ temp^T), symmetric half
        for (int idx = t16; idx < 182; idx += 16) {
            int kk = (idx >= 91) ? 1 : 0;
            int p = idx - kk * 91;
            int n = PN[p], m = PM[p];
            const float4* tn = reinterpret_cast<const float4*>(&R[kk * 208 + n * 16]);
            const float4* tm = reinterpret_cast<const float4*>(&R[kk * 208 + m * 16]);
            float s = 0.f;
            #pragma unroll
            for (int q = 0; q < 4; ++q) {
                float4 a = tn[q], bq = tm[q];
                s += a.x * bq.x + a.y * bq.y + a.z * bq.z + a.w * bq.w;
            }
            s = fmaxf(s, 0.f);
            Rc[kk * 169 + n * 13 + m] = s;
            Rc[kk * 169 + m * 13 + n] = s;
        }
        __syncwarp();
        // coalesced write: 338 floats = 169 float2
        {
            const float2* src2 = reinterpret_cast<const float2*>(Rc);
            float2* dst2 = reinterpret_cast<float2*>(outR + c * 338);
            for (int j = t16; j < 169; j += 16) dst2[j] = src2[j];
        }
        __syncwarp();
    }
}

extern "C" void kernel_launch(void* const* d_in, const int* in_sizes, int n_in,
                              void* d_out, int out_size) {
    (void)in_sizes; (void)n_in; (void)out_size;
    cudaFuncSetAttribute(vae_kernel, cudaFuncAttributeMaxDynamicSharedMemorySize, SMEM_BYTES);
    vae_kernel<<<32768 / NB, TPB, SMEM_BYTES>>>(
        (const float*)d_in[0],  (const float*)d_in[1],  (const float*)d_in[2],
        (const float*)d_in[3],  (const float*)d_in[4],  (const float*)d_in[5],
        (const float*)d_in[6],  (const float*)d_in[7],  (const float*)d_in[8],
        (const float*)d_in[9],  (const float*)d_in[10], (const float*)d_in[11],
        (const float*)d_in[12], (const float*)d_in[13], (const float*)d_in[14],
        (const float*)d_in[15], (const float*)d_in[16], (const float*)d_in[17],
        (const float*)d_in[18], (const float*)d_in[19], (const float*)d_in[20],
        (float*)d_out);
}

// round 14
// speedup vs baseline: 1.8389x; 1.8389x over previous
#include <cuda_runtime.h>

// Problem constants
#define NN 13          // nodes
#define DD 16          // feature dim
#define NB 16          // batch elements per block
#define TPB 128        // threads per block
#define TB 8           // threads per batch element (2 cols each)

// Per-batch shared region: stride 888 floats (888 % 32 == 24 -> 4 groups/warp at
// distinct bank offsets {0,24,16,8}).
//  [0..676)   adj (4ch x 13 x 13, unpadded)
//             decoder reuse: temp [0..208), recon scratch [208..377)
//  [680..888) xbuf (S matrix, then current features 13x16, then mu)
#define RS   888
#define XOFF 680

// Block-common weights region (after 16 per-b regions)
#define WB     14208
#define OW     (WB)            // init_weight [13][16]            208
#define OW0    (WB+208)        // w0 transposed [l][d'][c]       1024
#define OW1    (WB+1232)       // w1 transposed                  1024
#define OB0    (WB+2256)       // mlp_b0 [l][16]                   64
#define OB1    (WB+2320)       //                                  64
#define OF1    (WB+2384)       // fc1 transposed [d'][c]          256
#define OF2    (WB+2640)       //                                 256
#define OF1B   (WB+2896)       //                                  16
#define OF2B   (WB+2912)       //                                  16
#define ODEC   (WB+2928)       // dec transposed [k][l][d]       1024
#define ODECB  (WB+3952)       //                                  64
#define OBIS   (WB+4016)       // bn_in scale  [l][13]             52
#define OBIB   (WB+4068)       // bn_in bias                       52
#define OBOS   (WB+4120)       // bn_out scale                     52
#define OBOB   (WB+4172)       // bn_out bias                      52
#define OEPS   (WB+4224)       // 1+eps [4]                         4
#define SH_FLOATS (WB+4228)    // 18436 floats = 73744 B -> 3 blocks/SM
#define SMEM_BYTES (SH_FLOATS*4)

// Output layout: recon (B,4,13,13) | mu (B,13,16) | logvar (B,13,16)
#define RECON_ELEMS (676ull)
#define MU_OFF  (32768ull*676ull)          // 22151168
#define LV_OFF  (MU_OFF + 32768ull*208ull) // 28966912

// Triangular pair decode tables for p in [0,91): (n<=m)
__constant__ unsigned char PN[91] = {
 0,0,0,0,0,0,0,0,0,0,0,0,0,
 1,1,1,1,1,1,1,1,1,1,1,1,
 2,2,2,2,2,2,2,2,2,2,2,
 3,3,3,3,3,3,3,3,3,3,
 4,4,4,4,4,4,4,4,4,
 5,5,5,5,5,5,5,5,
 6,6,6,6,6,6,6,
 7,7,7,7,7,7,
 8,8,8,8,8,
 9,9,9,9,
 10,10,10,
 11,11,
 12};
__constant__ unsigned char PM[91] = {
 0,1,2,3,4,5,6,7,8,9,10,11,12,
 1,2,3,4,5,6,7,8,9,10,11,12,
 2,3,4,5,6,7,8,9,10,11,12,
 3,4,5,6,7,8,9,10,11,12,
 4,5,6,7,8,9,10,11,12,
 5,6,7,8,9,10,11,12,
 6,7,8,9,10,11,12,
 7,8,9,10,11,12,
 8,9,10,11,12,
 9,10,11,12,
 10,11,12,
 11,12,
 12};

__global__ void __launch_bounds__(TPB, 3) vae_kernel(
    const float* __restrict__ adj,
    const float* __restrict__ initW,
    const float* __restrict__ eps_param,
    const float* __restrict__ mlp_w0,
    const float* __restrict__ mlp_b0,
    const float* __restrict__ mlp_w1,
    const float* __restrict__ mlp_b1,
    const float* __restrict__ bn_in_gamma,
    const float* __restrict__ bn_in_beta,
    const float* __restrict__ bn_in_mean,
    const float* __restrict__ bn_in_var,
    const float* __restrict__ bn_out_gamma,
    const float* __restrict__ bn_out_beta,
    const float* __restrict__ bn_out_mean,
    const float* __restrict__ bn_out_var,
    const float* __restrict__ fc1_w,
    const float* __restrict__ fc1_b,
    const float* __restrict__ fc2_w,
    const float* __restrict__ fc2_b,
    const float* __restrict__ dec_w,
    const float* __restrict__ dec_b,
    float* __restrict__ out)
{
    extern __shared__ float sh[];
    const int tid = threadIdx.x;

    // ---------------- Phase A: cooperative loads ----------------
    {
        // adj: 16 b * 169 float4 (RS%4==0 so per-batch base stays 16B-aligned)
        const float4* src = reinterpret_cast<const float4*>(adj + (size_t)blockIdx.x * NB * 676);
        for (int c = tid; c < NB * 169; c += TPB) {
            int bl = c / 169;
            int r  = c - bl * 169;
            *reinterpret_cast<float4*>(&sh[bl * RS + r * 4]) = src[c];
        }
    }
    for (int j = tid; j < 208; j += TPB) sh[OW + j] = initW[j];
    for (int j = tid; j < 1024; j += TPB) {
        int l = j >> 8, r = j & 255, dp = r >> 4, c = r & 15;
        sh[OW0 + j] = mlp_w0[(l << 8) + (c << 4) + dp];
        sh[OW1 + j] = mlp_w1[(l << 8) + (c << 4) + dp];
        sh[ODEC + j] = dec_w[(l << 8) + (c << 4) + dp];
    }
    for (int j = tid; j < 64; j += TPB) {
        sh[OB0 + j] = mlp_b0[j];
        sh[OB1 + j] = mlp_b1[j];
        sh[ODECB + j] = dec_b[j];
    }
    for (int j = tid; j < 256; j += TPB) {
        int dp = j >> 4, c = j & 15;
        sh[OF1 + j] = fc1_w[(c << 4) + dp];
        sh[OF2 + j] = fc2_w[(c << 4) + dp];
    }
    for (int j = tid; j < 16; j += TPB) {
        sh[OF1B + j] = fc1_b[j];
        sh[OF2B + j] = fc2_b[j];
    }
    for (int j = tid; j < 52; j += TPB) {
        float s = bn_in_gamma[j] * rsqrtf(bn_in_var[j] + 1e-5f);
        sh[OBIS + j] = s;
        sh[OBIB + j] = bn_in_beta[j] - bn_in_mean[j] * s;
        float so = bn_out_gamma[j] * rsqrtf(bn_out_var[j] + 1e-5f);
        sh[OBOS + j] = so;
        sh[OBOB + j] = bn_out_beta[j] - bn_out_mean[j] * so;
    }
    for (int j = tid; j < 4; j += TPB) sh[OEPS + j] = 1.0f + eps_param[j];
    __syncthreads();

    // ---------------- Phase B: per-batch work (warp-local) ----------------
    const int lane = tid & 31;
    const int warp = tid >> 5;
    const int grp  = lane >> 3;       // batch within warp (0..3)
    const int t    = lane & 7;        // thread within batch, owns cols 2t, 2t+1
    const int bl   = warp * 4 + grp;
    const size_t b = (size_t)blockIdx.x * NB + bl;
    float* R  = sh + bl * RS;
    float* Xb = R + XOFF;
    const int d0  = 2 * t;
    const int iCh = t >> 1;           // adj channel for owned cols

    // S[n][m] = sum_i adj[i][n][m]  (into xbuf, safe: x not yet there)
    for (int p = t; p < 169; p += TB)
        Xb[p] = R[p] + R[169 + p] + R[338 + p] + R[507 + p];
    __syncwarp();

    float x0[NN], x1[NN];
    // x = S @ W
    #pragma unroll
    for (int n = 0; n < NN; ++n) {
        float a0 = 0.f, a1 = 0.f;
        #pragma unroll
        for (int m = 0; m < NN; ++m) {
            float s = Xb[n * 13 + m];
            float2 w = *reinterpret_cast<const float2*>(&sh[OW + m * 16 + d0]);
            a0 += s * w.x;
            a1 += s * w.y;
        }
        x0[n] = a0; x1[n] = a1;
    }

    // 4 GIN layers
    for (int l = 0; l < 4; ++l) {
        float ep = sh[OEPS + l];
        float h0[NN], h1[NN];
        const float* A = R + iCh * 169;
        #pragma unroll
        for (int n = 0; n < NN; ++n) {
            float a0 = 0.f, a1 = 0.f;
            #pragma unroll
            for (int m = 0; m < NN; ++m) {
                float av = A[n * 13 + m];
                a0 += av * x0[m];
                a1 += av * x1[m];
            }
            h0[n] = ep * x0[n] + a0;
            h1[n] = ep * x1[n] + a1;
        }
        __syncwarp();  // previous Xb readers done
        #pragma unroll
        for (int n = 0; n < NN; ++n)
            *reinterpret_cast<float2*>(&Xb[n * 16 + d0]) = make_float2(h0[n], h1[n]);
        __syncwarp();

        // MLP1 + bn_in + leaky
        {
            const float* Wt = sh + OW0 + (l << 8);
            float bb0 = sh[OB0 + (l << 4) + d0];
            float bb1 = sh[OB0 + (l << 4) + d0 + 1];
            #pragma unroll
            for (int n = 0; n < NN; ++n) {
                float a0 = bb0, a1 = bb1;
                #pragma unroll
                for (int dp = 0; dp < DD; ++dp) {
                    float xv = Xb[n * 16 + dp];
                    float2 w = *reinterpret_cast<const float2*>(&Wt[dp * 16 + d0]);
                    a0 += xv * w.x;
                    a1 += xv * w.y;
                }
                float sc = sh[OBIS + l * 13 + n], bi = sh[OBIB + l * 13 + n];
                a0 = a0 * sc + bi;
                a1 = a1 * sc + bi;
                h0[n] = (a0 >= 0.f) ? a0 : 0.01f * a0;
                h1[n] = (a1 >= 0.f) ? a1 : 0.01f * a1;
            }
        }
        __syncwarp();
        #pragma unroll
        for (int n = 0; n < NN; ++n)
            *reinterpret_cast<float2*>(&Xb[n * 16 + d0]) = make_float2(h0[n], h1[n]);
        __syncwarp();

        // MLP2 + bn_out + leaky -> new x
        {
            const float* Wt = sh + OW1 + (l << 8);
            float bb0 = sh[OB1 + (l << 4) + d0];
            float bb1 = sh[OB1 + (l << 4) + d0 + 1];
            #pragma unroll
            for (int n = 0; n < NN; ++n) {
                float a0 = bb0, a1 = bb1;
                #pragma unroll
                for (int dp = 0; dp < DD; ++dp) {
                    float xv = Xb[n * 16 + dp];
                    float2 w = *reinterpret_cast<const float2*>(&Wt[dp * 16 + d0]);
                    a0 += xv * w.x;
                    a1 += xv * w.y;
                }
                float sc = sh[OBOS + l * 13 + n], bi = sh[OBOB + l * 13 + n];
                a0 = a0 * sc + bi;
                a1 = a1 * sc + bi;
                x0[n] = (a0 >= 0.f) ? a0 : 0.01f * a0;
                x1[n] = (a1 >= 0.f) ? a1 : 0.01f * a1;
            }
        }
    }

    // fc1 -> mu, fc2 -> logvar
    __syncwarp();
    #pragma unroll
    for (int n = 0; n < NN; ++n)
        *reinterpret_cast<float2*>(&Xb[n * 16 + d0]) = make_float2(x0[n], x1[n]);
    __syncwarp();

    float mu0[NN], mu1[NN];
    {
        float fb0 = sh[OF1B + d0], fb1 = sh[OF1B + d0 + 1];
        #pragma unroll
        for (int n = 0; n < NN; ++n) {
            float a0 = fb0, a1 = fb1;
            #pragma unroll
            for (int dp = 0; dp < DD; ++dp) {
                float xv = Xb[n * 16 + dp];
                float2 w = *reinterpret_cast<const float2*>(&sh[OF1 + dp * 16 + d0]);
                a0 += xv * w.x;
                a1 += xv * w.y;
            }
            mu0[n] = a0; mu1[n] = a1;
        }
    }
    {
        float* muG = out + MU_OFF + b * 208;
        #pragma unroll
        for (int n = 0; n < NN; ++n)
            *reinterpret_cast<float2*>(&muG[n * 16 + d0]) = make_float2(mu0[n], mu1[n]);
    }
    {
        float fb0 = sh[OF2B + d0], fb1 = sh[OF2B + d0 + 1];
        float* lvG = out + LV_OFF + b * 208;
        #pragma unroll
        for (int n = 0; n < NN; ++n) {
            float a0 = fb0, a1 = fb1;
            #pragma unroll
            for (int dp = 0; dp < DD; ++dp) {
                float xv = Xb[n * 16 + dp];
                float2 w = *reinterpret_cast<const float2*>(&sh[OF2 + dp * 16 + d0]);
                a0 += xv * w.x;
                a1 += xv * w.y;
            }
            *reinterpret_cast<float2*>(&lvG[n * 16 + d0]) = make_float2(a0, a1);
        }
    }
    __syncwarp();   // fc reads of Xb done
    #pragma unroll
    for (int n = 0; n < NN; ++n)
        *reinterpret_cast<float2*>(&Xb[n * 16 + d0]) = make_float2(mu0[n], mu1[n]);
    __syncwarp();

    // Decoder in 4 single-k chunks: temp at R[0..208), recon scratch R[208..377)
    float* outR = out + b * RECON_ELEMS;
    float* T  = R;
    float* Rc = R + 208;
    #pragma unroll 1
    for (int k = 0; k < 4; ++k) {
        const float* Dt = sh + ODEC + (k << 8);
        float db0 = sh[ODECB + (k << 4) + d0];
        float db1 = sh[ODECB + (k << 4) + d0 + 1];
        #pragma unroll
        for (int n = 0; n < NN; ++n) {
            float a0 = db0, a1 = db1;
            #pragma unroll
            for (int li = 0; li < DD; ++li) {
                float mv = Xb[n * 16 + li];
                float2 w = *reinterpret_cast<const float2*>(&Dt[li * 16 + d0]);
                a0 += mv * w.x;
                a1 += mv * w.y;
            }
            *reinterpret_cast<float2*>(&T[n * 16 + d0]) = make_float2(a0, a1);
        }
        __syncwarp();
        // recon = relu(temp @ temp^T), symmetric half
        for (int p = t; p < 91; p += TB) {
            int n = PN[p], m = PM[p];
            const float4* tn = reinterpret_cast<const float4*>(&T[n * 16]);
            const float4* tm = reinterpret_cast<const float4*>(&T[m * 16]);
            float s = 0.f;
            #pragma unroll
            for (int q = 0; q < 4; ++q) {
                float4 a = tn[q], bq = tm[q];
                s += a.x * bq.x + a.y * bq.y + a.z * bq.z + a.w * bq.w;
            }
            s = fmaxf(s, 0.f);
            Rc[n * 13 + m] = s;
            Rc[m * 13 + n] = s;
        }
        __syncwarp();
        // write 169 floats
        for (int j = t; j < 169; j += TB) outR[k * 169 + j] = Rc[j];
        __syncwarp();
    }
}

extern "C" void kernel_launch(void* const* d_in, const int* in_sizes, int n_in,
                              void* d_out, int out_size) {
    (void)in_sizes; (void)n_in; (void)out_size;
    cudaFuncSetAttribute(vae_kernel, cudaFuncAttributeMaxDynamicSharedMemorySize, SMEM_BYTES);
    vae_kernel<<<32768 / NB, TPB, SMEM_BYTES>>>(
        (const float*)d_in[0],  (const float*)d_in[1],  (const float*)d_in[2],
        (const float*)d_in[3],  (const float*)d_in[4],  (const float*)d_in[5],
        (const float*)d_in[6],  (const float*)d_in[7],  (const float*)d_in[8],
        (const float*)d_in[9],  (const float*)d_in[10], (const float*)d_in[11],
        (const float*)d_in[12], (const float*)d_in[13], (const float*)d_in[14],
        (const float*)d_in[15], (const float*)d_in[16], (const float*)d_in[17],
        (const float*)d_in[18], (const float*)d_in[19], (const float*)d_in[20],
        (float*)d_out);
}